// round 17
// baseline (speedup 1.0000x reference)
#include <cuda_runtime.h>
#include <cuda_fp16.h>
#include <cstdint>

#define NB      96
#define MT      32
#define THREADS 256
#define NCTA    256

typedef unsigned long long ull;

// W2 fragments (fp16, single term): [J(16)][KT(16)][lane(32)] x uint4(a0..a3)
__device__ uint4 WFhi4[16 * 16 * 32];

// ---- helpers ----
__device__ __forceinline__ ull pack2(float x, float y) {
    ull r; asm("mov.b64 %0, {%1, %2};" : "=l"(r) : "f"(x), "f"(y)); return r;
}
__device__ __forceinline__ void unpack2(ull v, float& x, float& y) {
    asm("mov.b64 {%0, %1}, %2;" : "=f"(x), "=f"(y) : "l"(v));
}
__device__ __forceinline__ void ffma2(ull& d, ull a, ull b) {
    asm("fma.rn.f32x2 %0, %1, %2, %0;" : "+l"(d) : "l"(a), "l"(b));
}
// low 16 bits = f16(f0), high 16 = f16(f1)
__device__ __forceinline__ uint32_t f16_pair(float f0, float f1) {
    uint32_t v; asm("cvt.rn.f16x2.f32 %0, %1, %2;" : "=r"(v) : "f"(f1), "f"(f0)); return v;
}

// non-volatile: lets the compiler schedule loads across MMAs
#define MMA(D, A, B0, B1)                                                  \
    asm("mma.sync.aligned.m16n8k16.row.col.f32.f16.f16.f32 "               \
        "{%0,%1,%2,%3},{%4,%5,%6,%7},{%8,%9},{%0,%1,%2,%3};"               \
        : "+f"((D)[0]), "+f"((D)[1]), "+f"((D)[2]), "+f"((D)[3])           \
        : "r"((A).x), "r"((A).y), "r"((A).z), "r"((A).w),                  \
          "r"(B0), "r"(B1))

// ---- prepass: W2 fp32 -> fp16 fragments ----
__global__ void prep_kernel(const float* __restrict__ W2) {
    int j = blockIdx.x;          // 0..255 (output row)
    int kp = threadIdx.x;        // 0..127 (k-pair)
    int k = 2 * kp;
    float2 f = *reinterpret_cast<const float2*>(W2 + (size_t)j * 256 + k);
    uint32_t hv = f16_pair(f.x, f.y);
    int J = j >> 4, r = j & 15, KT = k >> 4, q = k & 15;
    int a = ((r >> 3) & 1) | ((q >> 3) << 1);
    int lane = ((r & 7) << 2) | ((q & 7) >> 1);
    int idx = ((((J * 16 + KT) * 32 + lane) << 2) | a);
    reinterpret_cast<uint32_t*>(WFhi4)[idx] = hv;
}

// ---- smem layout (bytes) ----
// BF: [kt16][lane32 x 48B] — per lane 4 uint2 (mt0..3) in 32B + 16B pad
#define OFF_BF   0        // 24576
#define OFF_W1J  24576    // 6144: [c][k] f32, k pair-contiguous
#define OFF_B1   30720    // 1024
#define OFF_XS   31744    // 1024: float XS[m32][8] = x0..x3, act, st, pad
#define OFF_RED  32768    // 1024: [warp8][m32] f32
#define SMEM_TOT 33792

__global__ __launch_bounds__(THREADS, 2)
void net_kernel(const float* __restrict__ X,      // [8192][96][4]
                const float* __restrict__ TN,     // [8192][96]
                const float* __restrict__ DN,     // [8192][96]
                const float* __restrict__ A0,     // [8192]
                const float* __restrict__ S0,     // [8192]
                const float* __restrict__ LAM,
                const float* __restrict__ BUD,
                const float* __restrict__ W1,     // [256][6]
                const float* __restrict__ B1,     // [256]
                const float* __restrict__ B2,     // [256]
                const float* __restrict__ W3,     // [256]
                const float* __restrict__ B3,     // [1]
                float* __restrict__ OUT)          // [8192][96]
{
    extern __shared__ __align__(16) char smem[];
    char*     BFc = smem + OFF_BF;
    float*    W1J = reinterpret_cast<float*>(smem + OFF_W1J);
    float*    B1s = reinterpret_cast<float*>(smem + OFF_B1);
    float*    XS  = reinterpret_cast<float*>(smem + OFF_XS);
    float*    RED = reinterpret_cast<float*>(smem + OFF_RED);

    const int tid  = threadIdx.x;
    const int w    = tid >> 5;
    const int lane = tid & 31;
    const int g    = lane >> 2;      // row-group within fragment
    const int q4   = lane & 3;       // col-group within fragment
    const int base = blockIdx.x * MT;

    // stage W1 transposed [c][k] and B1
    for (int i = tid; i < 6 * 256; i += THREADS) {
        int c = i >> 8, k = i & 255;
        W1J[c * 256 + k] = W1[k * 6 + c];
    }
    for (int i = tid; i < 256; i += THREADS) B1s[i] = B1[i];

    const float lam = LAM[0], bud = BUD[0];
    const float budH     = __fdiv_rn(bud, 96.0f);
    const float per_step = lam * 2.0f + budH;
    const float b3v = B3[0];

    // per-thread epilogue constants: j = w*32 + jt*16 + g + 8*h
    float b2r[2][2], w3r[2][2];
    #pragma unroll
    for (int jt = 0; jt < 2; jt++)
        #pragma unroll
        for (int h = 0; h < 2; h++) {
            int j = w * 32 + jt * 16 + g + 8 * h;
            b2r[jt][h] = B2[j];
            w3r[jt][h] = W3[j];
        }

    // register state (threads 0..31) + initial XS staging
    float act = 0.f, st = 0.f, bgt = per_step, cumc = 0.f, adp = 0.f, Sv = 0.f;
    const float4* xrow = reinterpret_cast<const float4*>(X + (size_t)(base + (tid & 31)) * (NB * 4));
    if (tid < MT) {
        act = A0[base + tid];
        st  = S0[base + tid];
        float4 xv = xrow[0];
        *reinterpret_cast<float4*>(&XS[tid * 8])     = xv;
        *reinterpret_cast<float2*>(&XS[tid * 8 + 4]) = make_float2(act, st);
    }

    // A-fragment pointers: warp's J tiles are 2w and 2w+1
    const uint4* pA0h = WFhi4 + ((2 * w) * 16) * 32 + lane;
    const uint4* pA1h = pA0h + 16 * 32;

    __syncthreads();

    for (int t = 0; t < NB; t++) {
        // ---- prefetch scalar-tail memory (consumed after the GEMM) ----
        float pf_tn = 0.f, pf_dn = 0.f;
        float4 pf_x = make_float4(0.f, 0.f, 0.f, 0.f);
        if (tid < MT) {
            pf_tn = TN[(size_t)(base + tid) * NB + t];
            pf_dn = DN[(size_t)(base + tid) * NB + t];
            int tn = (t + 1 < NB) ? t + 1 : NB - 1;
            pf_x = xrow[tn];
        }

        // ======== layer 1: produce h1 directly as fp16 B-fragments ========
        #pragma unroll 1
        for (int kk = 0; kk < 2; kk++) {
            const int kt = w * 2 + kk;
            const int k0 = kt * 16 + q4 * 2;     // r=0 k-pair
            const int k1 = k0 + 8;               // r=1 k-pair
            ull c0[7], c1[7];
            #pragma unroll
            for (int d = 0; d < 6; d++) {
                c0[d] = *reinterpret_cast<const ull*>(&W1J[d * 256 + k0]);
                c1[d] = *reinterpret_cast<const ull*>(&W1J[d * 256 + k1]);
            }
            c0[6] = *reinterpret_cast<const ull*>(&B1s[k0]);
            c1[6] = *reinterpret_cast<const ull*>(&B1s[k1]);
            uint2 bb[4];
            #pragma unroll
            for (int mt = 0; mt < 4; mt++) {
                const int m = mt * 8 + g;
                float4 va = *reinterpret_cast<const float4*>(&XS[m * 8]);
                float2 vb = *reinterpret_cast<const float2*>(&XS[m * 8 + 4]);
                ull x0 = pack2(va.x, va.x), x1 = pack2(va.y, va.y);
                ull x2 = pack2(va.z, va.z), x3 = pack2(va.w, va.w);
                ull x4 = pack2(vb.x, vb.x), x5 = pack2(vb.y, vb.y);
                // r = 0
                ull s = c0[6];
                ffma2(s, c0[0], x0); ffma2(s, c0[1], x1); ffma2(s, c0[2], x2);
                ffma2(s, c0[3], x3); ffma2(s, c0[4], x4); ffma2(s, c0[5], x5);
                float s0, s1; unpack2(s, s0, s1);
                uint32_t hv0 = f16_pair(fmaxf(s0, 0.0f), fmaxf(s1, 0.0f));
                // r = 1
                s = c1[6];
                ffma2(s, c1[0], x0); ffma2(s, c1[1], x1); ffma2(s, c1[2], x2);
                ffma2(s, c1[3], x3); ffma2(s, c1[4], x4); ffma2(s, c1[5], x5);
                unpack2(s, s0, s1);
                uint32_t hv1 = f16_pair(fmaxf(s0, 0.0f), fmaxf(s1, 0.0f));
                bb[mt] = make_uint2(hv0, hv1);
            }
            char* bp = BFc + kt * 1536 + lane * 48;
            *reinterpret_cast<uint4*>(bp) =
                make_uint4(bb[0].x, bb[0].y, bb[1].x, bb[1].y);
            *reinterpret_cast<uint4*>(bp + 16) =
                make_uint4(bb[2].x, bb[2].y, bb[3].x, bb[3].y);
        }
        __syncthreads();

        // ======== GEMM: single fp16 term ========
        float d[8][4];
        #pragma unroll
        for (int i = 0; i < 8; i++) { d[i][0] = 0.f; d[i][1] = 0.f; d[i][2] = 0.f; d[i][3] = 0.f; }

        #pragma unroll 2
        for (int kt = 0; kt < 16; kt++) {
            uint4 ah0 = pA0h[kt * 32];
            uint4 ah1 = pA1h[kt * 32];

            const char* bp = BFc + kt * 1536 + lane * 48;
            uint4 blo = *reinterpret_cast<const uint4*>(bp);
            uint4 bhi = *reinterpret_cast<const uint4*>(bp + 16);

            MMA(d[0], ah0, blo.x, blo.y);
            MMA(d[4], ah1, blo.x, blo.y);
            MMA(d[1], ah0, blo.z, blo.w);
            MMA(d[5], ah1, blo.z, blo.w);
            MMA(d[2], ah0, bhi.x, bhi.y);
            MMA(d[6], ah1, bhi.x, bhi.y);
            MMA(d[3], ah0, bhi.z, bhi.w);
            MMA(d[7], ah1, bhi.z, bhi.w);
        }

        // ======== epilogue: cm[m] = sum_j w3[j]*relu(D+b2) ========
        float cm[8];
        #pragma unroll
        for (int i = 0; i < 8; i++) cm[i] = 0.0f;
        #pragma unroll
        for (int jt = 0; jt < 2; jt++) {
            #pragma unroll
            for (int mt = 0; mt < 4; mt++) {
                const float* dd = d[jt * 4 + mt];
                cm[2 * mt]     += w3r[jt][0] * fmaxf(dd[0] + b2r[jt][0], 0.0f)
                                + w3r[jt][1] * fmaxf(dd[2] + b2r[jt][1], 0.0f);
                cm[2 * mt + 1] += w3r[jt][0] * fmaxf(dd[1] + b2r[jt][0], 0.0f)
                                + w3r[jt][1] * fmaxf(dd[3] + b2r[jt][1], 0.0f);
            }
        }
        #pragma unroll
        for (int off = 4; off <= 16; off <<= 1) {
            #pragma unroll
            for (int i = 0; i < 8; i++)
                cm[i] += __shfl_xor_sync(0xFFFFFFFFu, cm[i], off);
        }
        if (lane < 4) {
            #pragma unroll
            for (int mt = 0; mt < 4; mt++)
                *reinterpret_cast<float2*>(&RED[w * 32 + mt * 8 + lane * 2]) =
                    make_float2(cm[2 * mt], cm[2 * mt + 1]);
        }
        __syncthreads();

        // ======== scalar recurrence (threads 0..31, state in regs) ========
        if (tid < MT) {
            const int m = tid;
            float a_ml = b3v;
            #pragma unroll
            for (int ww = 0; ww < 8; ww++) a_ml += RED[ww * 32 + m];
            a_ml = fmaxf(a_ml, 0.0f);

            float demand = XS[m * 8];
            float a_prior = fminf(__fdiv_rn(fmaxf(st + demand, 0.0f), 0.8f), 10.0f);

            int n = 95 - t;
            float p = (n <= 63) ? __uint_as_float((unsigned)(127 - 2 * n) << 23) : 0.0f;
            float Gamma = 2.0f + 0.5f * (1.0f - p);

            float sgn = (a_ml < a_prior) ? 1.0f : -1.0f;
            float a_out = a_ml +
                fmaxf(fabsf(a_ml - a_prior) - __fdiv_rn(bgt, Gamma), 0.0f) * sgn;

            float ns = fminf(fmaxf(st * (1.0f - pf_dn) + demand
                                   - (0.8f + pf_tn) * a_out, 0.0f), 15.0f);
            float c_cost = 0.1f * ns * ns + ns + 2.0f;

            float ad_new = fabsf(a_out - a_prior);
            float Snew = 0.25f * Sv + ad_new;
            float cum_d = 2.0f * ad_new + 0.375f * Sv;
            float c_prior = fmaxf(2.0f, c_cost - cum_d);
            float cum_c_new = cumc + (1.0f + lam) * c_prior - c_cost;
            float cum_d_g = 0.5f * Snew * (1.0f - p);

            float bgt_if = fmaxf(fmaxf(bgt + per_step - ad_new * Gamma, 0.0f),
                                 cum_c_new - cum_d_g + lam * 2.0f + budH * (float)(t + 2));
            float bgt_else = fmaxf(bgt + per_step - adp * Gamma, 0.0f);

            bool last = (t == NB - 1);
            bgt  = last ? bgt_else : bgt_if;
            cumc = last ? cumc : cum_c_new;
            adp  = ad_new;
            act  = a_out;
            st   = ns;
            Sv   = Snew;
            OUT[(size_t)(base + m) * NB + t] = a_out;

            // stage XS for t+1 from prefetched X
            *reinterpret_cast<float4*>(&XS[m * 8])     = pf_x;
            *reinterpret_cast<float2*>(&XS[m * 8 + 4]) = make_float2(act, st);
        }
        __syncthreads();
    }
}

extern "C" void kernel_launch(void* const* d_in, const int* in_sizes, int n_in,
                              void* d_out, int out_size) {
    (void)in_sizes; (void)n_in; (void)out_size;
    cudaFuncSetAttribute(net_kernel, cudaFuncAttributeMaxDynamicSharedMemorySize, SMEM_TOT);
    prep_kernel<<<256, 128>>>((const float*)d_in[9]);   // W2
    net_kernel<<<NCTA, THREADS, SMEM_TOT>>>(
        (const float*)d_in[0],   // policy_in_c
        (const float*)d_in[1],   // trans_noise
        (const float*)d_in[2],   // demand_noise
        (const float*)d_in[3],   // action_pre
        (const float*)d_in[4],   // state_pre
        (const float*)d_in[5],   // Lambda
        (const float*)d_in[6],   // Budget
        (const float*)d_in[7],   // W1
        (const float*)d_in[8],   // b1
        (const float*)d_in[10],  // b2
        (const float*)d_in[11],  // W3
        (const float*)d_in[12],  // b3
        (float*)d_out);
}